// round 11
// baseline (speedup 1.0000x reference)
#include <cuda_runtime.h>
#include <cuda_bf16.h>
#include <cstdint>

// CTC batch cost, B=512 T=512 C=128 L=32, S=65, blank=127.
// Probability-domain forward recursion, per-lane power-of-two exponent frames.
// NEW: sector-compacted streaming — each CTA computes the set of 32B sectors
// its labels (plus blank) actually touch (~14 of 16 on average) and loaders
// cp.async only those sectors, cutting DRAM bytes ~12.5%. Compute warp reads
// via remapped compacted column indices; values are bit-identical to full-row.
// 4-stage cp.async ring (round-6 proven schedule), 1 recursion warp per CTA
// spread across SMSPs via (b/148)&3, 3 loader warps.

namespace {
constexpr int Bsz = 512;
constexpr int Tsz = 512;
constexpr int Csz = 128;
constexpr int Lsz = 32;
constexpr int TC   = 16;             // timesteps per stage
constexpr int NCH  = Tsz / TC;       // 32 chunks
constexpr int NST  = 4;              // ring stages
constexpr int STBY = TC * 16 * 32;   // stage stride: worst case 16 sectors = 8 KB
constexpr float LN2F = 0.69314718055994530942f;
constexpr float EPSF = 1e-7f;
}

__device__ __forceinline__ float ex2f_(float x) {
    float r; asm("ex2.approx.ftz.f32 %0, %1;" : "=f"(r) : "f"(x)); return r;
}
__device__ __forceinline__ float lg2f_(float x) {
    float r; asm("lg2.approx.ftz.f32 %0, %1;" : "=f"(r) : "f"(x)); return r;
}
__device__ __forceinline__ void cpasync16(uint32_t dst, const void* src) {
    asm volatile("cp.async.cg.shared.global [%0], [%1], 16;" :: "r"(dst), "l"(src));
}
__device__ __forceinline__ void cpcommit() {
    asm volatile("cp.async.commit_group;");
}
template <int N> __device__ __forceinline__ void cpwait() {
    asm volatile("cp.async.wait_group %0;" :: "n"(N));
}

__global__ __launch_bounds__(128, 4)
void ctc_loss_kernel(const int* __restrict__ y_true,
                     const float* __restrict__ y_pred,
                     float* __restrict__ out)
{
    __shared__ float raw[NST][STBY / 4];   // 32 KB ring (compacted rows)
    __shared__ int   lab[Lsz];

    const int b    = blockIdx.x;
    const int tid  = threadIdx.x;
    const int wid  = tid >> 5;
    const int lane = tid & 31;
    const int rw   = (b / 148) & 3;     // co-resident CTAs -> different SMSPs

    if (tid < Lsz) lab[tid] = y_true[b * Lsz + tid];
    __syncthreads();

    // ---- per-CTA sector set (uniform across threads) ----
    unsigned mask = 1u << 15;                    // blank sector always needed
    #pragma unroll
    for (int i = 0; i < Lsz; ++i) mask |= 1u << (lab[i] >> 3);
    const int nsec = __popc(mask);               // 2..16
    uint64_t packed = 0;                         // nibble r = sector id of rank r
    { int r = 0;
      for (int s = 0; s < 16; ++s)
          if (mask & (1u << s)) { packed |= (uint64_t)s << (4 * r); ++r; } }
    const int pitchF = nsec * 8;                 // floats per compacted row

    const bool isComp = (wid == rw);
    int lrank = 0;
    if (!isComp) lrank = ((wid > rw) ? wid - 1 : wid) * 32 + lane;  // 0..95

    const uint32_t rawBase = (uint32_t)__cvta_generic_to_shared(&raw[0][0]);
    const char*    src0    = (const char*)(y_pred + (long)b * Tsz * Csz);
    const int      nsec2   = nsec * 2;           // 16B halves per row
    const int      cnt     = TC * nsec2;         // cp.asyncs per stage

    auto issueChunk = [&](int c) {
        const char* src = src0 + (long)c * TC * (Csz * 4);
        uint32_t dst = rawBase + (uint32_t)(c & (NST - 1)) * STBY;
        for (int i = lrank; i < cnt; i += 96) {
            int t = i / nsec2;
            int j = i - t * nsec2;
            int sec = (int)((packed >> (4 * (j >> 1))) & 15);
            cpasync16(dst + (uint32_t)(t * (nsec * 32) + j * 16),
                      src + t * 512 + sec * 32 + (j & 1) * 16);
        }
        cpcommit();
    };

    if (!isComp) {
        issueChunk(0); issueChunk(1); issueChunk(2);
        cpwait<2>();
    }
    __syncthreads();

    // recursion state (probability domain, per-lane frames)
    float a0 = 0.0f, a1 = 0.0f, a2 = 0.0f;
    float skipM = 0.0f, scaleRot = 1.0f, skipRotM = 0.0f;
    int   myCol = 0, blankCol = 0, laneSrc = 0, shift = 0;
    if (isComp) {
        int ml   = lab[lane];
        myCol    = __popc(mask & ((1u << (ml >> 3)) - 1u)) * 8 + (ml & 7);
        blankCol = (nsec - 1) * 8 + 7;           // sector 15 is last; class 127
        skipM    = (lane >= 1 && ml != lab[lane - 1]) ? 1.0f : 0.0f;
        skipRotM = skipM;
        laneSrc  = (lane + 31) & 31;             // rotate: lane l <- lane (l-1)%32
    }

    for (int c = 0; c < NCH; ++c) {
        if (isComp) {
            const float* rawf = &raw[c & (NST - 1)][0];
            int t0 = 0;
            if (c == 0) {
                float pb = rawf[blankCol] + EPSF;
                float pl = rawf[myCol]    + EPSF;
                a0 = (lane == 0) ? pb : 0.0f;
                a1 = (lane == 0) ? pl : 0.0f;
                t0 = 1;
            }
            #pragma unroll
            for (int tt = t0; tt < TC; ++tt) {
                const float* row = rawf + tt * pitchF;
                float pb = row[blankCol] + EPSF;   // blank prob (broadcast LDS)
                float pl = row[myCol]    + EPSF;   // label prob (scattered LDS)

                float rv   = __shfl_sync(0xffffffffu, a1, laneSrc);
                float tsum = a1 + a0;

                // odd slot: a1 = (a1 + a0 + skip*alpha[2l-1]) * pl
                a1 = __fmaf_rn(rv, skipRotM, tsum) * pl;

                // even slot: lanes>=1 update a0; lane 0 updates a2 (s=64)
                float rot = rv * scaleRot;
                float x   = (lane == 0) ? a2 : a0;
                float r0  = (x + rot) * pb;
                if (lane == 0) { a2 = r0; a0 = a0 * pb; }
                else           { a0 = r0; }
            }

            if (c & 1) {
                // per-lane renorm + frame exchange (every 32 steps)
                float m = fmaxf(fmaxf(a0, a1), a2);   // a2==0 on lanes != 0
                int e = 0;
                if (m > 0.0f) e = (int)(__float_as_uint(m) >> 23) - 127;
                if (e > 126) e = 126;
                float sc = __uint_as_float((unsigned)(127 - e) << 23); // 2^-e
                a0 *= sc; a1 *= sc; a2 *= sc;
                shift += e;

                int shSrc = __shfl_sync(0xffffffffu, shift, laneSrc);
                if (m == 0.0f) shift = shSrc;       // dead lane adopts frame
                int d = shSrc - shift;
                d = (d > 126) ? 126 : d;
                scaleRot = (d < -126) ? 0.0f
                         : __uint_as_float((unsigned)(127 + d) << 23);  // 2^d
                skipRotM = skipM * scaleRot;
            }
        } else {
            if (c + 3 < NCH)      { issueChunk(c + 3); cpwait<2>(); }
            else if (c + 2 < NCH) { cpwait<1>(); }
            else if (c + 1 < NCH) { cpwait<0>(); }
        }
        __syncthreads();
    }

    if (isComp) {
        // log2 of alpha_T[S-1] (lane 0: a2) and alpha_T[S-2] (lane 31: a1)
        float v  = lg2f_((lane == 31) ? a1 : a2) + (float)shift;
        float v1 = __shfl_sync(0xffffffffu, v, 31);
        if (lane == 0) {
            float mm = fmaxf(v, v1);
            float dd = fabsf(v - v1);
            out[b] = -LN2F * (mm + lg2f_(1.0f + ex2f_(-dd)));
        }
    }
}

extern "C" void kernel_launch(void* const* d_in, const int* in_sizes, int n_in,
                              void* d_out, int out_size)
{
    const int*   y_true = (const int*)d_in[0];    // [512, 32] int32
    const float* y_pred = (const float*)d_in[1];  // [512, 512, 128] float32
    float*       out    = (float*)d_out;          // [512, 1] float32
    (void)in_sizes; (void)n_in; (void)out_size;

    ctc_loss_kernel<<<Bsz, 128>>>(y_true, y_pred, out);
}

// round 12
// speedup vs baseline: 1.1391x; 1.1391x over previous
#include <cuda_runtime.h>
#include <cuda_bf16.h>
#include <cstdint>

// CTC batch cost, B=512 T=512 C=128 L=32, S=65, blank=127.
// Probability-domain forward recursion, per-lane power-of-two exponent frames.
// Sector-compacted streaming with PRECOMPUTED loader offsets: each CTA's
// label set touches ~14 of 16 sectors per 512B row; each loader thread
// precomputes its <=6 (dst,src) offset pairs once, so the steady-state loop
// is pure cp.async issue (no div/mod/nibble math per copy).
// 4-stage cp.async ring (round-6 schedule), 1 recursion warp per CTA spread
// across SMSPs via (b/148)&3, 3 loader warps.

namespace {
constexpr int Bsz = 512;
constexpr int Tsz = 512;
constexpr int Csz = 128;
constexpr int Lsz = 32;
constexpr int TC   = 16;             // timesteps per stage
constexpr int NCH  = Tsz / TC;       // 32 chunks
constexpr int NST  = 4;              // ring stages
constexpr int STBY = TC * 16 * 32;   // stage stride (worst case 16 sectors) = 8 KB
constexpr int MAXK = 6;              // max cp.asyncs per loader thread per chunk
constexpr float LN2F = 0.69314718055994530942f;
constexpr float EPSF = 1e-7f;
}

__device__ __forceinline__ float ex2f_(float x) {
    float r; asm("ex2.approx.ftz.f32 %0, %1;" : "=f"(r) : "f"(x)); return r;
}
__device__ __forceinline__ float lg2f_(float x) {
    float r; asm("lg2.approx.ftz.f32 %0, %1;" : "=f"(r) : "f"(x)); return r;
}
__device__ __forceinline__ void cpasync16(uint32_t dst, const void* src) {
    asm volatile("cp.async.cg.shared.global [%0], [%1], 16;" :: "r"(dst), "l"(src));
}
__device__ __forceinline__ void cpcommit() {
    asm volatile("cp.async.commit_group;");
}
template <int N> __device__ __forceinline__ void cpwait() {
    asm volatile("cp.async.wait_group %0;" :: "n"(N));
}

__global__ __launch_bounds__(128, 4)
void ctc_loss_kernel(const int* __restrict__ y_true,
                     const float* __restrict__ y_pred,
                     float* __restrict__ out)
{
    __shared__ float raw[NST][STBY / 4];   // 32 KB ring (compacted rows)
    __shared__ int   lab[Lsz];

    const int b    = blockIdx.x;
    const int tid  = threadIdx.x;
    const int wid  = tid >> 5;
    const int lane = tid & 31;
    const int rw   = (b / 148) & 3;     // co-resident CTAs -> different SMSPs

    if (tid < Lsz) lab[tid] = y_true[b * Lsz + tid];
    __syncthreads();

    // ---- per-CTA sector set (uniform across threads) ----
    unsigned mask = 1u << 15;                    // blank sector always needed
    #pragma unroll
    for (int i = 0; i < Lsz; ++i) mask |= 1u << (lab[i] >> 3);
    const int nsec = __popc(mask);               // 2..16
    uint64_t packed = 0;                         // nibble r = sector id of rank r
    { int r = 0;
      for (int s = 0; s < 16; ++s)
          if (mask & (1u << s)) { packed |= (uint64_t)s << (4 * r); ++r; } }
    const int pitchF = nsec * 8;                 // floats per compacted row

    const bool isComp = (wid == rw);
    int lrank = 0;
    if (!isComp) lrank = ((wid > rw) ? wid - 1 : wid) * 32 + lane;  // 0..95

    const uint32_t rawBase = (uint32_t)__cvta_generic_to_shared(&raw[0][0]);
    const char*    src0    = (const char*)(y_pred + (long)b * Tsz * Csz);
    const int      nsec2   = nsec * 2;           // 16B halves per row
    const int      cnt     = TC * nsec2;         // cp.asyncs per stage (<=512)

    // ---- precompute per-thread copy offsets (fixed pattern, all chunks) ----
    int      nOps = 0;
    uint32_t dOff[MAXK];
    int      sOff[MAXK];
    if (!isComp) {
        #pragma unroll
        for (int k = 0; k < MAXK; ++k) {
            int i = lrank + 96 * k;
            if (i < cnt) {
                int t   = i / nsec2;                       // runtime div, once
                int j   = i - t * nsec2;
                int sec = (int)((packed >> (4 * (j >> 1))) & 15);
                dOff[nOps] = (uint32_t)(t * (nsec * 32) + j * 16);
                sOff[nOps] = t * 512 + sec * 32 + (j & 1) * 16;
                ++nOps;
            }
        }
    }

    auto issueChunk = [&](int c) {
        const char* src = src0 + (long)c * TC * 512;
        uint32_t dst = rawBase + (uint32_t)(c & (NST - 1)) * STBY;
        #pragma unroll
        for (int k = 0; k < MAXK; ++k)
            if (k < nOps) cpasync16(dst + dOff[k], src + sOff[k]);
        cpcommit();
    };

    if (!isComp) {
        issueChunk(0); issueChunk(1); issueChunk(2);
        cpwait<2>();
    }
    __syncthreads();

    // recursion state (probability domain, per-lane frames)
    float a0 = 0.0f, a1 = 0.0f, a2 = 0.0f;
    float skipM = 0.0f, scaleRot = 1.0f, skipRotM = 0.0f;
    int   myCol = 0, blankCol = 0, laneSrc = 0, shift = 0;
    if (isComp) {
        int ml   = lab[lane];
        myCol    = __popc(mask & ((1u << (ml >> 3)) - 1u)) * 8 + (ml & 7);
        blankCol = (nsec - 1) * 8 + 7;           // sector 15 is last; class 127
        skipM    = (lane >= 1 && ml != lab[lane - 1]) ? 1.0f : 0.0f;
        skipRotM = skipM;
        laneSrc  = (lane + 31) & 31;             // rotate: lane l <- lane (l-1)%32
    }

    for (int c = 0; c < NCH; ++c) {
        if (isComp) {
            const float* rawf = &raw[c & (NST - 1)][0];
            int t0 = 0;
            if (c == 0) {
                float pb = rawf[blankCol] + EPSF;
                float pl = rawf[myCol]    + EPSF;
                a0 = (lane == 0) ? pb : 0.0f;
                a1 = (lane == 0) ? pl : 0.0f;
                t0 = 1;
            }
            #pragma unroll
            for (int tt = t0; tt < TC; ++tt) {
                const float* row = rawf + tt * pitchF;
                float pb = row[blankCol] + EPSF;   // blank prob (broadcast LDS)
                float pl = row[myCol]    + EPSF;   // label prob (scattered LDS)

                float rv   = __shfl_sync(0xffffffffu, a1, laneSrc);
                float tsum = a1 + a0;

                // odd slot: a1 = (a1 + a0 + skip*alpha[2l-1]) * pl
                a1 = __fmaf_rn(rv, skipRotM, tsum) * pl;

                // even slot: lanes>=1 update a0; lane 0 updates a2 (s=64)
                float rot = rv * scaleRot;
                float x   = (lane == 0) ? a2 : a0;
                float r0  = (x + rot) * pb;
                if (lane == 0) { a2 = r0; a0 = a0 * pb; }
                else           { a0 = r0; }
            }

            if (c & 1) {
                // per-lane renorm + frame exchange (every 32 steps)
                float m = fmaxf(fmaxf(a0, a1), a2);   // a2==0 on lanes != 0
                int e = 0;
                if (m > 0.0f) e = (int)(__float_as_uint(m) >> 23) - 127;
                if (e > 126) e = 126;
                float sc = __uint_as_float((unsigned)(127 - e) << 23); // 2^-e
                a0 *= sc; a1 *= sc; a2 *= sc;
                shift += e;

                int shSrc = __shfl_sync(0xffffffffu, shift, laneSrc);
                if (m == 0.0f) shift = shSrc;       // dead lane adopts frame
                int d = shSrc - shift;
                d = (d > 126) ? 126 : d;
                scaleRot = (d < -126) ? 0.0f
                         : __uint_as_float((unsigned)(127 + d) << 23);  // 2^d
                skipRotM = skipM * scaleRot;
            }
        } else {
            if (c + 3 < NCH)      { issueChunk(c + 3); cpwait<2>(); }
            else if (c + 2 < NCH) { cpwait<1>(); }
            else if (c + 1 < NCH) { cpwait<0>(); }
        }
        __syncthreads();
    }

    if (isComp) {
        // log2 of alpha_T[S-1] (lane 0: a2) and alpha_T[S-2] (lane 31: a1)
        float v  = lg2f_((lane == 31) ? a1 : a2) + (float)shift;
        float v1 = __shfl_sync(0xffffffffu, v, 31);
        if (lane == 0) {
            float mm = fmaxf(v, v1);
            float dd = fabsf(v - v1);
            out[b] = -LN2F * (mm + lg2f_(1.0f + ex2f_(-dd)));
        }
    }
}

extern "C" void kernel_launch(void* const* d_in, const int* in_sizes, int n_in,
                              void* d_out, int out_size)
{
    const int*   y_true = (const int*)d_in[0];    // [512, 32] int32
    const float* y_pred = (const float*)d_in[1];  // [512, 512, 128] float32
    float*       out    = (float*)d_out;          // [512, 1] float32
    (void)in_sizes; (void)n_in; (void)out_size;

    ctc_loss_kernel<<<Bsz, 128>>>(y_true, y_pred, out);
}

// round 14
// speedup vs baseline: 1.2243x; 1.0748x over previous
#include <cuda_runtime.h>
#include <cuda_bf16.h>
#include <cstdint>

// CTC batch cost, B=512 T=512 C=128 L=32, S=65, blank=127.
// Probability-domain forward recursion, per-lane power-of-two exponent frames
// (renorm every 32 steps). SINGLE-WARP CTA: lane 0 issues cp.async.bulk (TMA)
// copies of full 8KB chunks (16 rows x 512B) into a 4-stage SMEM ring with
// per-stage mbarriers; the same warp runs the alpha chain, waiting on the
// stage mbarrier (usually already complete). No loader warps, no syncthreads,
// no LDGSTS issue bottleneck.

namespace {
constexpr int Bsz = 512;
constexpr int Tsz = 512;
constexpr int Csz = 128;
constexpr int Lsz = 32;
constexpr int TC   = 16;               // timesteps per stage
constexpr int NCH  = Tsz / TC;         // 32 chunks
constexpr int NST  = 4;                // ring stages
constexpr int STBY = TC * Csz * 4;     // 8192 bytes per stage
constexpr float LN2F = 0.69314718055994530942f;
constexpr float EPSF = 1e-7f;
}

__device__ __forceinline__ float ex2f_(float x) {
    float r; asm("ex2.approx.ftz.f32 %0, %1;" : "=f"(r) : "f"(x)); return r;
}
__device__ __forceinline__ float lg2f_(float x) {
    float r; asm("lg2.approx.ftz.f32 %0, %1;" : "=f"(r) : "f"(x)); return r;
}
__device__ __forceinline__ void mbarInit(uint32_t mbar, unsigned cnt) {
    asm volatile("mbarrier.init.shared.b64 [%0], %1;" :: "r"(mbar), "r"(cnt) : "memory");
}
__device__ __forceinline__ void mbarExpectTx(uint32_t mbar, unsigned bytes) {
    asm volatile("mbarrier.arrive.expect_tx.shared.b64 _, [%0], %1;"
                 :: "r"(mbar), "r"(bytes) : "memory");
}
__device__ __forceinline__ void bulkLoad(uint32_t dst, const void* src,
                                         unsigned bytes, uint32_t mbar) {
    asm volatile(
        "cp.async.bulk.shared::cta.global.mbarrier::complete_tx::bytes "
        "[%0], [%1], %2, [%3];"
        :: "r"(dst), "l"(src), "r"(bytes), "r"(mbar) : "memory");
}
__device__ __forceinline__ void mbarWait(uint32_t mbar, unsigned parity) {
    asm volatile(
        "{\n\t"
        ".reg .pred P;\n\t"
        "W_%=:\n\t"
        "mbarrier.try_wait.parity.acquire.cta.shared::cta.b64 P, [%0], %1;\n\t"
        "@!P bra W_%=;\n\t"
        "}"
        :: "r"(mbar), "r"(parity) : "memory");
}

__global__ __launch_bounds__(32)
void ctc_loss_kernel(const int* __restrict__ y_true,
                     const float* __restrict__ y_pred,
                     float* __restrict__ out)
{
    __shared__ alignas(16) float    raw[NST][STBY / 4];   // 32 KB ring
    __shared__ alignas(8)  uint64_t mbar[NST];

    const int b    = blockIdx.x;
    const int lane = threadIdx.x & 31;

    const uint32_t rawBase  = (uint32_t)__cvta_generic_to_shared(&raw[0][0]);
    const uint32_t mbarBase = (uint32_t)__cvta_generic_to_shared(&mbar[0]);
    const char*    src0     = (const char*)(y_pred + (long)b * Tsz * Csz);

    if (lane == 0) {
        #pragma unroll
        for (int s = 0; s < NST; ++s) mbarInit(mbarBase + 8u * s, 1u);
    }
    __syncwarp();
    // make mbarrier inits visible to the async (TMA) proxy
    asm volatile("fence.proxy.async.shared::cta;" ::: "memory");

    auto issueChunk = [&](int c) {
        uint32_t mb = mbarBase + 8u * (c & (NST - 1));
        mbarExpectTx(mb, (unsigned)STBY);
        bulkLoad(rawBase + (uint32_t)(c & (NST - 1)) * STBY,
                 src0 + (long)c * STBY, (unsigned)STBY, mb);
    };

    if (lane == 0) { issueChunk(0); issueChunk(1); issueChunk(2); }
    __syncwarp();

    // recursion state (probability domain, per-lane frames)
    const int myLab = y_true[b * Lsz + lane];
    const int prvLab = __shfl_up_sync(0xffffffffu, myLab, 1);
    const float skipM = (lane >= 1 && myLab != prvLab) ? 1.0f : 0.0f;
    const int laneSrc = (lane + 31) & 31;   // rotate: lane l <- lane (l-1)%32

    float a0 = 0.0f, a1 = 0.0f, a2 = 0.0f;
    float scaleRot = 1.0f, skipRotM = skipM;
    int   shift = 0;

    for (int c = 0; c < NCH; ++c) {
        if (lane == 0 && c + 3 < NCH) issueChunk(c + 3);
        mbarWait(mbarBase + 8u * (c & (NST - 1)), (unsigned)((c >> 2) & 1));

        const float* rawf = &raw[c & (NST - 1)][0];
        int t0 = 0;
        if (c == 0) {
            float pb = rawf[Csz - 1] + EPSF;
            float pl = rawf[myLab]   + EPSF;
            a0 = (lane == 0) ? pb : 0.0f;
            a1 = (lane == 0) ? pl : 0.0f;
            t0 = 1;
        }
        #pragma unroll
        for (int tt = t0; tt < TC; ++tt) {
            const float* row = rawf + tt * Csz;
            float pb = row[Csz - 1] + EPSF;   // blank prob (broadcast LDS)
            float pl = row[myLab]   + EPSF;   // label prob (scattered LDS)

            float rv   = __shfl_sync(0xffffffffu, a1, laneSrc);
            float tsum = a1 + a0;

            // odd slot: a1 = (a1 + a0 + skip*alpha[2l-1]) * pl
            a1 = __fmaf_rn(rv, skipRotM, tsum) * pl;

            // even slot: lanes>=1 update a0; lane 0 updates a2 (s=64)
            float rot = rv * scaleRot;
            float x   = (lane == 0) ? a2 : a0;
            float r0  = (x + rot) * pb;
            if (lane == 0) { a2 = r0; a0 = a0 * pb; }
            else           { a0 = r0; }
        }

        if (c & 1) {
            // per-lane renorm + frame exchange (every 32 steps)
            float m = fmaxf(fmaxf(a0, a1), a2);   // a2==0 on lanes != 0
            int e = 0;
            if (m > 0.0f) e = (int)(__float_as_uint(m) >> 23) - 127;
            if (e > 126) e = 126;
            float sc = __uint_as_float((unsigned)(127 - e) << 23); // 2^-e
            a0 *= sc; a1 *= sc; a2 *= sc;
            shift += e;

            int shSrc = __shfl_sync(0xffffffffu, shift, laneSrc);
            if (m == 0.0f) shift = shSrc;       // dead lane adopts frame
            int d = shSrc - shift;
            d = (d > 126) ? 126 : d;
            scaleRot = (d < -126) ? 0.0f
                     : __uint_as_float((unsigned)(127 + d) << 23);  // 2^d
            skipRotM = skipM * scaleRot;
        }
    }

    // log2 of alpha_T[S-1] (lane 0: a2) and alpha_T[S-2] (lane 31: a1)
    float v  = lg2f_((lane == 31) ? a1 : a2) + (float)shift;
    float v1 = __shfl_sync(0xffffffffu, v, 31);
    if (lane == 0) {
        float mm = fmaxf(v, v1);
        float dd = fabsf(v - v1);
        out[b] = -LN2F * (mm + lg2f_(1.0f + ex2f_(-dd)));
    }
}

extern "C" void kernel_launch(void* const* d_in, const int* in_sizes, int n_in,
                              void* d_out, int out_size)
{
    const int*   y_true = (const int*)d_in[0];    // [512, 32] int32
    const float* y_pred = (const float*)d_in[1];  // [512, 512, 128] float32
    float*       out    = (float*)d_out;          // [512, 1] float32
    (void)in_sizes; (void)n_in; (void)out_size;

    ctc_loss_kernel<<<Bsz, 32>>>(y_true, y_pred, out);
}